// round 5
// baseline (speedup 1.0000x reference)
#include <cuda_runtime.h>
#include <stdint.h>

// atom_eng[c] = FACTOR * sum_{edges e} edge_eng[e] * scales[sp[c], sp[nbr]]
// E=6.4M, N=100K. Species nibbles staged in SMEM. R5: 256thr/block,
// launch_bounds(256,4) -> 64-reg budget, UNROLL=3 front-batched LDG.128s
// (R4 failed because 512thr/full-occ capped regs at 32 and serialized loads).

#define FACTOR 0.125f  // 1/sqrt(64)
#define UNROLL 3

__device__ uint32_t g_packed_species[32768];  // up to 262144 nodes

__global__ void prep_kernel(const int* __restrict__ species,
                            float* __restrict__ out,
                            int N, int nwords) {
    int i = blockIdx.x * blockDim.x + threadIdx.x;
    if (i < N) out[i] = 0.0f;
    if (i < nwords) {
        uint32_t w = 0;
        int base = i << 3;
        #pragma unroll
        for (int k = 0; k < 8; k++) {
            int idx = base + k;
            if (idx < N) w |= ((uint32_t)species[idx] & 0xFu) << (k << 2);
        }
        g_packed_species[i] = w;
    }
}

__global__ __launch_bounds__(256, 4) void edge_energy_sum_kernel(
    const float* __restrict__ edge_eng,     // [E]
    const float* __restrict__ scales,       // [256]
    const int*   __restrict__ ei_center,    // [E]
    const int*   __restrict__ ei_neighbor,  // [E]
    float* __restrict__ out,                // [N]
    int E, int nwords)
{
    extern __shared__ uint32_t smem[];
    float*    s_scale = (float*)smem;   // 256 floats
    uint32_t* s_pack  = smem + 256;     // nwords words

    if (threadIdx.x < 256) s_scale[threadIdx.x] = scales[threadIdx.x] * FACTOR;
    for (int i = threadIdx.x; i < nwords; i += blockDim.x)
        s_pack[i] = g_packed_species[i];
    __syncthreads();

    int nvec = E >> 2;
    int tid = blockIdx.x * blockDim.x + threadIdx.x;
    int stride = gridDim.x * blockDim.x;

    const float4* eng4 = (const float4*)edge_eng;
    const int4*   c4   = (const int4*)ei_center;
    const int4*   n4   = (const int4*)ei_neighbor;

    #define SPEC(idx) ((s_pack[(idx) >> 3] >> (((idx) & 7) << 2)) & 0xFu)

    int v = tid;
    // Batched main loop: UNROLL*3 independent LDG.128 issued before any consume.
    for (; v + (UNROLL - 1) * stride < nvec; v += UNROLL * stride) {
        float4 e[UNROLL];
        int4   c[UNROLL];
        int4   n[UNROLL];
        #pragma unroll
        for (int u = 0; u < UNROLL; u++) {
            int idx = v + u * stride;
            e[u] = __ldcs(&eng4[idx]);
            c[u] = __ldcs(&c4[idx]);
            n[u] = __ldcs(&n4[idx]);
        }
        #pragma unroll
        for (int u = 0; u < UNROLL; u++) {
            float v0 = e[u].x * s_scale[(SPEC(c[u].x) << 4) | SPEC(n[u].x)];
            float v1 = e[u].y * s_scale[(SPEC(c[u].y) << 4) | SPEC(n[u].y)];
            float v2 = e[u].z * s_scale[(SPEC(c[u].z) << 4) | SPEC(n[u].z)];
            float v3 = e[u].w * s_scale[(SPEC(c[u].w) << 4) | SPEC(n[u].w)];
            atomicAdd(&out[c[u].x], v0);
            atomicAdd(&out[c[u].y], v1);
            atomicAdd(&out[c[u].z], v2);
            atomicAdd(&out[c[u].w], v3);
        }
    }
    // Remaining vec4 groups for this thread.
    for (; v < nvec; v += stride) {
        float4 e = __ldcs(&eng4[v]);
        int4   c = __ldcs(&c4[v]);
        int4   n = __ldcs(&n4[v]);
        float v0 = e.x * s_scale[(SPEC(c.x) << 4) | SPEC(n.x)];
        float v1 = e.y * s_scale[(SPEC(c.y) << 4) | SPEC(n.y)];
        float v2 = e.z * s_scale[(SPEC(c.z) << 4) | SPEC(n.z)];
        float v3 = e.w * s_scale[(SPEC(c.w) << 4) | SPEC(n.w)];
        atomicAdd(&out[c.x], v0);
        atomicAdd(&out[c.y], v1);
        atomicAdd(&out[c.z], v2);
        atomicAdd(&out[c.w], v3);
    }

    // Scalar tail (E not divisible by 4)
    int base = nvec << 2;
    for (int i = base + tid; i < E; i += stride) {
        int cc = ei_center[i];
        int nn = ei_neighbor[i];
        float val = edge_eng[i] * s_scale[(SPEC(cc) << 4) | SPEC(nn)];
        atomicAdd(&out[cc], val);
    }
    #undef SPEC
}

extern "C" void kernel_launch(void* const* d_in, const int* in_sizes, int n_in,
                              void* d_out, int out_size) {
    const float* edge_eng = (const float*)d_in[0];  // [E,1]
    const float* scales   = (const float*)d_in[1];  // [16,16]
    const int*   edge_idx = (const int*)d_in[2];    // [2,E]
    const int*   species  = (const int*)d_in[3];    // [N]
    float* out = (float*)d_out;

    int E = in_sizes[0];
    int N = out_size;
    int nwords = (N + 7) >> 3;

    const int* ei_center   = edge_idx;
    const int* ei_neighbor = edge_idx + E;

    size_t smem_bytes = 256 * sizeof(float) + (size_t)nwords * sizeof(uint32_t);
    cudaFuncSetAttribute(edge_energy_sum_kernel,
                         cudaFuncAttributeMaxDynamicSharedMemorySize,
                         (int)smem_bytes);

    int prep_n = (N > nwords ? N : nwords);
    prep_kernel<<<(prep_n + 255) / 256, 256>>>(species, out, N, nwords);

    int threads = 256;
    int blocks = 148 * 4;
    int nvec = E >> 2;
    int need = (nvec + threads - 1) / threads;
    if (blocks > need) blocks = need > 0 ? need : 1;
    edge_energy_sum_kernel<<<blocks, threads, smem_bytes>>>(
        edge_eng, scales, ei_center, ei_neighbor, out, E, nwords);
}

// round 6
// speedup vs baseline: 1.0936x; 1.0936x over previous
#include <cuda_runtime.h>
#include <stdint.h>

// out[c] = FACTOR * sum_e eng[e] * scales[sp[c], sp[n]]
// Factored:  pass1: tmp[c*16 + sp[n]] += eng[e]   (1 LDS + 1 RED per edge)
//            pass2: out[c] = FACTOR * dot(scales[sp[c],:], tmp[c,:])
// E=6.4M, N=100K. MIO/RED-throughput bound per R3-R5 ncu.

#define FACTOR 0.125f  // 1/sqrt(64)

__device__ uint32_t g_packed_species[32768];   // nibble-packed species, up to 262144 nodes
__device__ float    g_tmp[262144 * 16];        // per-(node, neighbor-species) accumulators

// Zero tmp and pack species nibbles.
__global__ void prep_kernel(const int* __restrict__ species,
                            int N, int nwords, int ntmp) {
    int i = blockIdx.x * blockDim.x + threadIdx.x;
    if (i < ntmp) g_tmp[i] = 0.0f;
    if (i < nwords) {
        uint32_t w = 0;
        int base = i << 3;
        #pragma unroll
        for (int k = 0; k < 8; k++) {
            int idx = base + k;
            if (idx < N) w |= ((uint32_t)species[idx] & 0xFu) << (k << 2);
        }
        g_packed_species[i] = w;
    }
}

// Pass 1: scatter edge energies into (center, neighbor-species) bins.
__global__ __launch_bounds__(512) void edge_scatter_kernel(
    const float* __restrict__ edge_eng,     // [E]
    const int*   __restrict__ ei_center,    // [E]
    const int*   __restrict__ ei_neighbor,  // [E]
    int E, int nwords)
{
    extern __shared__ uint32_t s_pack[];    // nwords words (~50KB)
    for (int i = threadIdx.x; i < nwords; i += blockDim.x)
        s_pack[i] = g_packed_species[i];
    __syncthreads();

    #define SPEC(idx) ((s_pack[(idx) >> 3] >> (((idx) & 7) << 2)) & 0xFu)

    int nvec = E >> 2;
    int tid = blockIdx.x * blockDim.x + threadIdx.x;
    int stride = gridDim.x * blockDim.x;

    const float4* eng4 = (const float4*)edge_eng;
    const int4*   c4   = (const int4*)ei_center;
    const int4*   n4   = (const int4*)ei_neighbor;

    for (int v = tid; v < nvec; v += stride) {
        float4 e = __ldcs(&eng4[v]);
        int4   c = __ldcs(&c4[v]);
        int4   n = __ldcs(&n4[v]);
        atomicAdd(&g_tmp[(c.x << 4) | SPEC(n.x)], e.x);
        atomicAdd(&g_tmp[(c.y << 4) | SPEC(n.y)], e.y);
        atomicAdd(&g_tmp[(c.z << 4) | SPEC(n.z)], e.z);
        atomicAdd(&g_tmp[(c.w << 4) | SPEC(n.w)], e.w);
    }

    int base = nvec << 2;
    for (int i = base + tid; i < E; i += stride) {
        int cc = ei_center[i];
        int nn = ei_neighbor[i];
        atomicAdd(&g_tmp[(cc << 4) | SPEC(nn)], edge_eng[i]);
    }
    #undef SPEC
}

// Pass 2: per-node dot product with the species-pair scale row.
__global__ __launch_bounds__(256) void node_reduce_kernel(
    const float* __restrict__ scales,   // [256]
    const int*   __restrict__ species,  // [N]
    float* __restrict__ out,            // [N]
    int N)
{
    __shared__ float s_scale[256];
    if (threadIdx.x < 256) s_scale[threadIdx.x] = scales[threadIdx.x];
    __syncthreads();

    int i = blockIdx.x * blockDim.x + threadIdx.x;
    if (i >= N) return;

    int sc = species[i] & 0xF;
    const float* srow = &s_scale[sc << 4];
    const float4* t = (const float4*)&g_tmp[i << 4];

    float4 t0 = t[0], t1 = t[1], t2 = t[2], t3 = t[3];
    float acc = 0.0f;
    acc += t0.x * srow[0]  + t0.y * srow[1]  + t0.z * srow[2]  + t0.w * srow[3];
    acc += t1.x * srow[4]  + t1.y * srow[5]  + t1.z * srow[6]  + t1.w * srow[7];
    acc += t2.x * srow[8]  + t2.y * srow[9]  + t2.z * srow[10] + t2.w * srow[11];
    acc += t3.x * srow[12] + t3.y * srow[13] + t3.z * srow[14] + t3.w * srow[15];
    out[i] = acc * FACTOR;
}

extern "C" void kernel_launch(void* const* d_in, const int* in_sizes, int n_in,
                              void* d_out, int out_size) {
    const float* edge_eng = (const float*)d_in[0];  // [E,1]
    const float* scales   = (const float*)d_in[1];  // [16,16]
    const int*   edge_idx = (const int*)d_in[2];    // [2,E]
    const int*   species  = (const int*)d_in[3];    // [N]
    float* out = (float*)d_out;

    int E = in_sizes[0];
    int N = out_size;
    int nwords = (N + 7) >> 3;
    int ntmp = N << 4;

    const int* ei_center   = edge_idx;
    const int* ei_neighbor = edge_idx + E;

    size_t smem_bytes = (size_t)nwords * sizeof(uint32_t);
    cudaFuncSetAttribute(edge_scatter_kernel,
                         cudaFuncAttributeMaxDynamicSharedMemorySize,
                         (int)smem_bytes);

    int prep_n = (ntmp > nwords ? ntmp : nwords);
    prep_kernel<<<(prep_n + 255) / 256, 256>>>(species, N, nwords, ntmp);

    int threads = 512;
    int blocks = 148 * 4;
    int nvec = E >> 2;
    int need = (nvec + threads - 1) / threads;
    if (blocks > need) blocks = need > 0 ? need : 1;
    edge_scatter_kernel<<<blocks, threads, smem_bytes>>>(
        edge_eng, ei_center, ei_neighbor, E, nwords);

    node_reduce_kernel<<<(N + 255) / 256, 256>>>(scales, species, out, N);
}

// round 7
// speedup vs baseline: 1.1034x; 1.0089x over previous
#include <cuda_runtime.h>
#include <stdint.h>

// out[c] = FACTOR * sum_e eng[e] * scales[sp[c], sp[n]]
// pass1: tmp[c*16 + sp[n]] += eng[e]   (1 LDS + 1 RED per edge)
// pass2: out[c] = FACTOR * dot(scales[sp[c],:], tmp[c,:])
// R7: prep was 6.9us (launch/scalar-bound); replace with cudaMemsetAsync +
// tiny vectorized pack kernel. Scatter/reduce unchanged (near REDG floor).

#define FACTOR 0.125f  // 1/sqrt(64)

__device__ uint32_t g_packed_species[32768];   // nibble-packed species (<=262144 nodes)
__device__ float    g_tmp[262144 * 16];        // (node, neighbor-species) accumulators

// Pack species into nibbles; int4-vectorized (each thread packs 8 species).
__global__ void pack_kernel(const int* __restrict__ species, int N, int nwords) {
    int i = blockIdx.x * blockDim.x + threadIdx.x;
    if (i >= nwords) return;
    int base = i << 3;
    uint32_t w = 0;
    if (base + 8 <= N) {
        int4 a = *(const int4*)&species[base];
        int4 b = *(const int4*)&species[base + 4];
        w  = ((uint32_t)a.x & 0xFu)
           | (((uint32_t)a.y & 0xFu) << 4)
           | (((uint32_t)a.z & 0xFu) << 8)
           | (((uint32_t)a.w & 0xFu) << 12)
           | (((uint32_t)b.x & 0xFu) << 16)
           | (((uint32_t)b.y & 0xFu) << 20)
           | (((uint32_t)b.z & 0xFu) << 24)
           | (((uint32_t)b.w & 0xFu) << 28);
    } else {
        for (int k = 0; k < 8; k++) {
            int idx = base + k;
            if (idx < N) w |= ((uint32_t)species[idx] & 0xFu) << (k << 2);
        }
    }
    g_packed_species[i] = w;
}

// Pass 1: scatter edge energies into (center, neighbor-species) bins.
__global__ __launch_bounds__(512) void edge_scatter_kernel(
    const float* __restrict__ edge_eng,     // [E]
    const int*   __restrict__ ei_center,    // [E]
    const int*   __restrict__ ei_neighbor,  // [E]
    int E, int nwords)
{
    extern __shared__ uint32_t s_pack[];    // nwords words (~50KB)
    for (int i = threadIdx.x; i < nwords; i += blockDim.x)
        s_pack[i] = g_packed_species[i];
    __syncthreads();

    #define SPEC(idx) ((s_pack[(idx) >> 3] >> (((idx) & 7) << 2)) & 0xFu)

    int nvec = E >> 2;
    int tid = blockIdx.x * blockDim.x + threadIdx.x;
    int stride = gridDim.x * blockDim.x;

    const float4* eng4 = (const float4*)edge_eng;
    const int4*   c4   = (const int4*)ei_center;
    const int4*   n4   = (const int4*)ei_neighbor;

    for (int v = tid; v < nvec; v += stride) {
        float4 e = __ldcs(&eng4[v]);
        int4   c = __ldcs(&c4[v]);
        int4   n = __ldcs(&n4[v]);
        atomicAdd(&g_tmp[(c.x << 4) | SPEC(n.x)], e.x);
        atomicAdd(&g_tmp[(c.y << 4) | SPEC(n.y)], e.y);
        atomicAdd(&g_tmp[(c.z << 4) | SPEC(n.z)], e.z);
        atomicAdd(&g_tmp[(c.w << 4) | SPEC(n.w)], e.w);
    }

    int base = nvec << 2;
    for (int i = base + tid; i < E; i += stride) {
        int cc = ei_center[i];
        int nn = ei_neighbor[i];
        atomicAdd(&g_tmp[(cc << 4) | SPEC(nn)], edge_eng[i]);
    }
    #undef SPEC
}

// Pass 2: per-node dot product with the species-pair scale row.
__global__ __launch_bounds__(256) void node_reduce_kernel(
    const float* __restrict__ scales,   // [256]
    const int*   __restrict__ species,  // [N]
    float* __restrict__ out,            // [N]
    int N)
{
    __shared__ float s_scale[256];
    if (threadIdx.x < 256) s_scale[threadIdx.x] = scales[threadIdx.x];
    __syncthreads();

    int i = blockIdx.x * blockDim.x + threadIdx.x;
    if (i >= N) return;

    int sc = species[i] & 0xF;
    const float* srow = &s_scale[sc << 4];
    const float4* t = (const float4*)&g_tmp[i << 4];

    float4 t0 = t[0], t1 = t[1], t2 = t[2], t3 = t[3];
    float acc = 0.0f;
    acc += t0.x * srow[0]  + t0.y * srow[1]  + t0.z * srow[2]  + t0.w * srow[3];
    acc += t1.x * srow[4]  + t1.y * srow[5]  + t1.z * srow[6]  + t1.w * srow[7];
    acc += t2.x * srow[8]  + t2.y * srow[9]  + t2.z * srow[10] + t2.w * srow[11];
    acc += t3.x * srow[12] + t3.y * srow[13] + t3.z * srow[14] + t3.w * srow[15];
    out[i] = acc * FACTOR;
}

extern "C" void kernel_launch(void* const* d_in, const int* in_sizes, int n_in,
                              void* d_out, int out_size) {
    const float* edge_eng = (const float*)d_in[0];  // [E,1]
    const float* scales   = (const float*)d_in[1];  // [16,16]
    const int*   edge_idx = (const int*)d_in[2];    // [2,E]
    const int*   species  = (const int*)d_in[3];    // [N]
    float* out = (float*)d_out;

    int E = in_sizes[0];
    int N = out_size;
    int nwords = (N + 7) >> 3;

    const int* ei_center   = edge_idx;
    const int* ei_neighbor = edge_idx + E;

    // Zero only the used part of tmp via driver memset (graph-capturable).
    void* tmp_ptr = nullptr;
    cudaGetSymbolAddress(&tmp_ptr, g_tmp);
    cudaMemsetAsync(tmp_ptr, 0, (size_t)N * 16 * sizeof(float), 0);

    pack_kernel<<<(nwords + 255) / 256, 256>>>(species, N, nwords);

    size_t smem_bytes = (size_t)nwords * sizeof(uint32_t);
    cudaFuncSetAttribute(edge_scatter_kernel,
                         cudaFuncAttributeMaxDynamicSharedMemorySize,
                         (int)smem_bytes);

    int threads = 512;
    int blocks = 148 * 4;
    int nvec = E >> 2;
    int need = (nvec + threads - 1) / threads;
    if (blocks > need) blocks = need > 0 ? need : 1;
    edge_scatter_kernel<<<blocks, threads, smem_bytes>>>(
        edge_eng, ei_center, ei_neighbor, E, nwords);

    node_reduce_kernel<<<(N + 255) / 256, 256>>>(scales, species, out, N);
}